// round 1
// baseline (speedup 1.0000x reference)
#include <cuda_runtime.h>
#include <math.h>

#define BB 256
#define LL 200
#define NN 256
#define DD 16
#define KSUB 8

// Output layout: xhat | mu | logvar | z_traj | zdiff  (all float32)
#define OFF_XHAT 0
#define OFF_MU   (BB*LL*NN)
#define OFF_LV   (OFF_MU + BB*DD)
#define OFF_ZT   (OFF_LV + BB*DD)
#define OFF_ZD   (OFF_ZT + BB*LL*DD)

// decoder intermediate g2 = relu(relu(z W1+b1) W2 + b2): 51200 x 512 fp32
__device__ float g_g2[51200 * 512];

__device__ __forceinline__ float siluf(float x) {
    return x / (1.f + expf(-x));
}

// ---------------------------------------------------------------------------
// Encoder: one CTA per batch row, 256 threads.
// ---------------------------------------------------------------------------
__global__ void __launch_bounds__(256)
enc_kernel(const float* __restrict__ x_seq,
           const float* __restrict__ eps,
           const float* __restrict__ w1, const float* __restrict__ b1,
           const float* __restrict__ w2, const float* __restrict__ b2,
           const float* __restrict__ w3, const float* __restrict__ b3,
           const float* __restrict__ muw, const float* __restrict__ mub,
           const float* __restrict__ lvw, const float* __restrict__ lvb,
           float* __restrict__ out)
{
    __shared__ float x0[256];
    __shared__ float h1[512];
    __shared__ float h2[256];
    __shared__ float h3[128];
    const int b = blockIdx.x;
    const int t = threadIdx.x;

    x0[t] = x_seq[(size_t)b * (LL * NN) + t];  // x_seq[b, 0, t]
    __syncthreads();

    for (int c = t; c < 512; c += 256) {
        float acc = b1[c];
#pragma unroll 8
        for (int j = 0; j < 256; j++) acc = fmaf(x0[j], w1[j * 512 + c], acc);
        h1[c] = fmaxf(acc, 0.f);
    }
    __syncthreads();

    {
        float acc = b2[t];
#pragma unroll 8
        for (int j = 0; j < 512; j++) acc = fmaf(h1[j], w2[j * 256 + t], acc);
        h2[t] = fmaxf(acc, 0.f);
    }
    __syncthreads();

    if (t < 128) {
        float acc = b3[t];
#pragma unroll 8
        for (int j = 0; j < 256; j++) acc = fmaf(h2[j], w3[j * 128 + t], acc);
        h3[t] = fmaxf(acc, 0.f);
    }
    __syncthreads();

    if (t < 16) {
        float m = mub[t];
        float lv = lvb[t];
#pragma unroll 8
        for (int j = 0; j < 128; j++) {
            m  = fmaf(h3[j], muw[j * 16 + t], m);
            lv = fmaf(h3[j], lvw[j * 16 + t], lv);
        }
        out[OFF_MU + b * DD + t] = m;
        out[OFF_LV + b * DD + t] = lv;
        float z0 = m + expf(0.5f * lv) * eps[b * DD + t];
        out[OFF_ZT + (size_t)b * (LL * DD) + t] = z0;  // z_traj[b, 0, :]
    }
}

// ---------------------------------------------------------------------------
// ODE integrator: one CTA per batch row, 128 threads, persistent over all
// 199 intervals * 8 substeps * 6 dopri stages. W1/W2/W3 columns live in
// registers; RK state (z, k1..k5) replicated per 16-lane segment in regs.
// 3 __syncthreads per stage.
// ---------------------------------------------------------------------------
__global__ void __launch_bounds__(128, 2)
ode_kernel(const float* __restrict__ tvec,
           const float* __restrict__ w1, const float* __restrict__ b1,
           const float* __restrict__ w2, const float* __restrict__ b2,
           const float* __restrict__ w3, const float* __restrict__ b3,
           const float* __restrict__ lng, const float* __restrict__ lnb,
           float* __restrict__ out)
{
    const int t    = threadIdx.x;
    const int b    = blockIdx.x;
    const int lane = t & 31;
    const int l16  = lane & 15;

    // register-resident weights
    float w1c[16];
#pragma unroll
    for (int j = 0; j < 16; j++) w1c[j] = w1[j * 128 + t];
    const float b1t = b1[t];
    float w2c[128];
#pragma unroll
    for (int j = 0; j < 128; j++) w2c[j] = w2[j * 128 + t];
    const float b2t = b2[t];
    const int oo = t >> 3, gg = t & 7;  // 16 outputs x 8 partial-threads
    float w3p[16];
#pragma unroll
    for (int m = 0; m < 16; m++) w3p[m] = w3[(gg * 16 + m) * 16 + oo];
    const float b3o = b3[oo];
    const float lgv = lng[l16];
    const float lbv = lnb[l16];

    __shared__ float h1s[128];
    __shared__ float a2sp[136];  // stride-17 padded per 16 to avoid bank conflicts
    __shared__ float dzs[16];

    float* zrow = out + OFF_ZT + (size_t)b * (LL * DD);
    float zcur = zrow[l16];  // z0 written by encoder

    float k1 = 0.f, k2 = 0.f, k3 = 0.f, k4 = 0.f, k5 = 0.f;

    for (int iv = 0; iv < LL - 1; iv++) {
        const float h = (tvec[iv + 1] - tvec[iv]) * (1.f / (float)KSUB);
        for (int sub = 0; sub < KSUB; sub++) {
#pragma unroll
            for (int s = 0; s < 6; s++) {
                // --- stage input (replicated per 16-lane segment, registers only)
                float zin;
                if (s == 0)      zin = zcur;
                else if (s == 1) zin = zcur + h * (0.2f * k1);
                else if (s == 2) zin = zcur + h * (0.075f * k1 + 0.225f * k2);
                else if (s == 3) zin = zcur + h * ((44.f/45.f)*k1 - (56.f/15.f)*k2 + (32.f/9.f)*k3);
                else if (s == 4) zin = zcur + h * ((19372.f/6561.f)*k1 - (25360.f/2187.f)*k2
                                                 + (64448.f/6561.f)*k3 - (212.f/729.f)*k4);
                else             zin = zcur + h * ((9017.f/3168.f)*k1 - (355.f/33.f)*k2
                                                 + (46732.f/5247.f)*k3 + (49.f/176.f)*k4
                                                 - (5103.f/18656.f)*k5);

                // --- layer 1: h1[t] = silu(W1^T zin + b1)
                float acc = b1t;
#pragma unroll
                for (int j = 0; j < 16; j++) {
                    float zj = __shfl_sync(0xffffffffu, zin, j, 16);
                    acc = fmaf(zj, w1c[j], acc);
                }
                h1s[t] = siluf(acc);
                __syncthreads();  // B: h1 ready (also guards prev-stage a2s reads)

                // --- layer 2: a2[t] = silu(W2^T h1 + b2), W2 column in regs
                float p0 = 0.f, p1 = 0.f, p2 = 0.f, p3 = 0.f;
                const float4* h4 = (const float4*)h1s;
#pragma unroll
                for (int jj = 0; jj < 32; jj++) {
                    float4 hv = h4[jj];
                    p0 = fmaf(hv.x, w2c[4*jj+0], p0);
                    p1 = fmaf(hv.y, w2c[4*jj+1], p1);
                    p2 = fmaf(hv.z, w2c[4*jj+2], p2);
                    p3 = fmaf(hv.w, w2c[4*jj+3], p3);
                }
                float s2 = b2t + ((p0 + p1) + (p2 + p3));
                a2sp[t + (t >> 4)] = siluf(s2);
                __syncthreads();  // C: a2 ready

                // --- layer 3 partials: dz[oo] = sum_j a2[j] * W3[j][oo] + b3[oo]
                float p = 0.f;
                const int base = gg * 17;
#pragma unroll
                for (int m = 0; m < 16; m++)
                    p = fmaf(a2sp[base + m], w3p[m], p);
                p += __shfl_down_sync(0xffffffffu, p, 4, 8);
                p += __shfl_down_sync(0xffffffffu, p, 2, 8);
                p += __shfl_down_sync(0xffffffffu, p, 1, 8);
                if (gg == 0) dzs[oo] = p + b3o;
                __syncthreads();  // D: dz ready

                // --- LayerNorm + k update, replicated in every 16-lane segment
                float dv = dzs[l16];
                float mn = dv;
                mn += __shfl_xor_sync(0xffffffffu, mn, 8, 16);
                mn += __shfl_xor_sync(0xffffffffu, mn, 4, 16);
                mn += __shfl_xor_sync(0xffffffffu, mn, 2, 16);
                mn += __shfl_xor_sync(0xffffffffu, mn, 1, 16);
                mn *= (1.f / 16.f);
                float cd = dv - mn;
                float vv = cd * cd;
                vv += __shfl_xor_sync(0xffffffffu, vv, 8, 16);
                vv += __shfl_xor_sync(0xffffffffu, vv, 4, 16);
                vv += __shfl_xor_sync(0xffffffffu, vv, 2, 16);
                vv += __shfl_xor_sync(0xffffffffu, vv, 1, 16);
                vv *= (1.f / 16.f);
                float kv = cd * rsqrtf(vv + 1e-5f) * lgv + lbv;

                if (s == 0)      k1 = kv;
                else if (s == 1) k2 = kv;
                else if (s == 2) k3 = kv;
                else if (s == 3) k4 = kv;
                else if (s == 4) k5 = kv;
                else {
                    zcur = zcur + h * ((35.f/384.f)*k1 + (500.f/1113.f)*k3
                                     + (125.f/192.f)*k4 - (2187.f/6784.f)*k5
                                     + (11.f/84.f)*kv);
                }
            }
        }
        if (t < 16) zrow[(iv + 1) * DD + t] = zcur;
    }
}

// ---------------------------------------------------------------------------
// Decoder stage 1: g2 = relu(relu(z W1 + b1) W2 + b2). 16-row tiles.
// ---------------------------------------------------------------------------
__global__ void __launch_bounds__(512)
dec1_kernel(const float* __restrict__ ztraj,
            const float* __restrict__ w1, const float* __restrict__ b1,
            const float* __restrict__ w2, const float* __restrict__ b2)
{
    __shared__ float zts[16 * 16];
    __shared__ float g1s[16 * 512];  // 32 KB
    const int t = threadIdx.x;
    const int row0 = blockIdx.x * 16;

    if (t < 256) zts[t] = ztraj[(size_t)row0 * 16 + t];
    float w1r[16];
#pragma unroll
    for (int k = 0; k < 16; k++) w1r[k] = w1[k * 512 + t];
    const float b1v = b1[t];
    __syncthreads();

#pragma unroll
    for (int r = 0; r < 16; r++) {
        const float4* z4 = (const float4*)(zts + r * 16);
        float acc = b1v;
#pragma unroll
        for (int q = 0; q < 4; q++) {
            float4 zv = z4[q];
            acc = fmaf(zv.x, w1r[4*q+0], acc);
            acc = fmaf(zv.y, w1r[4*q+1], acc);
            acc = fmaf(zv.z, w1r[4*q+2], acc);
            acc = fmaf(zv.w, w1r[4*q+3], acc);
        }
        g1s[r * 512 + t] = fmaxf(acc, 0.f);
    }
    __syncthreads();

    float acc[16];
    const float bv = b2[t];
#pragma unroll
    for (int r = 0; r < 16; r++) acc[r] = bv;

    for (int j0 = 0; j0 < 512; j0 += 4) {
        const float wv0 = w2[(j0 + 0) * 512 + t];
        const float wv1 = w2[(j0 + 1) * 512 + t];
        const float wv2 = w2[(j0 + 2) * 512 + t];
        const float wv3 = w2[(j0 + 3) * 512 + t];
#pragma unroll
        for (int r = 0; r < 16; r++) {
            const float4 gv = *(const float4*)(g1s + r * 512 + j0);
            acc[r] = fmaf(gv.x, wv0, acc[r]);
            acc[r] = fmaf(gv.y, wv1, acc[r]);
            acc[r] = fmaf(gv.z, wv2, acc[r]);
            acc[r] = fmaf(gv.w, wv3, acc[r]);
        }
    }
#pragma unroll
    for (int r = 0; r < 16; r++)
        g_g2[(size_t)(row0 + r) * 512 + t] = fmaxf(acc[r], 0.f);
}

// ---------------------------------------------------------------------------
// Decoder stage 2: xhat = g2 W3 + b3. 16-row tiles.
// ---------------------------------------------------------------------------
__global__ void __launch_bounds__(256)
dec2_kernel(const float* __restrict__ w3, const float* __restrict__ b3,
            float* __restrict__ out)
{
    __shared__ float g2s[16 * 512];  // 32 KB
    const int t = threadIdx.x;
    const int row0 = blockIdx.x * 16;

#pragma unroll
    for (int i = 0; i < 32; i++)
        g2s[i * 256 + t] = g_g2[(size_t)row0 * 512 + i * 256 + t];
    __syncthreads();

    float acc[16];
    const float bv = b3[t];
#pragma unroll
    for (int r = 0; r < 16; r++) acc[r] = bv;

    for (int j0 = 0; j0 < 512; j0 += 4) {
        const float wv0 = w3[(j0 + 0) * 256 + t];
        const float wv1 = w3[(j0 + 1) * 256 + t];
        const float wv2 = w3[(j0 + 2) * 256 + t];
        const float wv3 = w3[(j0 + 3) * 256 + t];
#pragma unroll
        for (int r = 0; r < 16; r++) {
            const float4 gv = *(const float4*)(g2s + r * 512 + j0);
            acc[r] = fmaf(gv.x, wv0, acc[r]);
            acc[r] = fmaf(gv.y, wv1, acc[r]);
            acc[r] = fmaf(gv.z, wv2, acc[r]);
            acc[r] = fmaf(gv.w, wv3, acc[r]);
        }
    }
#pragma unroll
    for (int r = 0; r < 16; r++)
        out[OFF_XHAT + (size_t)(row0 + r) * 256 + t] = acc[r];
}

// ---------------------------------------------------------------------------
// zdiff = (z_traj[:,1:,:] - z_traj[:,:-1,:]) / dt
// ---------------------------------------------------------------------------
__global__ void zdiff_kernel(const float* __restrict__ tvec, float* __restrict__ out)
{
    const int idx = blockIdx.x * blockDim.x + threadIdx.x;
    const int total = BB * (LL - 1) * DD;
    if (idx >= total) return;
    const int o = idx & 15;
    const int rest = idx >> 4;
    const int i = rest % (LL - 1);
    const int b = rest / (LL - 1);
    const float dt = tvec[i + 1] - tvec[i];
    const float* zr = out + OFF_ZT + (size_t)b * (LL * DD);
    out[OFF_ZD + idx] = (zr[(i + 1) * DD + o] - zr[i * DD + o]) / dt;
}

// ---------------------------------------------------------------------------
extern "C" void kernel_launch(void* const* d_in, const int* in_sizes, int n_in,
                              void* d_out, int out_size)
{
    const float* x_seq  = (const float*)d_in[0];
    const float* tvec   = (const float*)d_in[1];
    const float* eps    = (const float*)d_in[2];
    const float* enc_w1 = (const float*)d_in[3];
    const float* enc_b1 = (const float*)d_in[4];
    const float* enc_w2 = (const float*)d_in[5];
    const float* enc_b2 = (const float*)d_in[6];
    const float* enc_w3 = (const float*)d_in[7];
    const float* enc_b3 = (const float*)d_in[8];
    const float* mu_w   = (const float*)d_in[9];
    const float* mu_b   = (const float*)d_in[10];
    const float* lv_w   = (const float*)d_in[11];
    const float* lv_b   = (const float*)d_in[12];
    const float* ode_w1 = (const float*)d_in[13];
    const float* ode_b1 = (const float*)d_in[14];
    const float* ode_w2 = (const float*)d_in[15];
    const float* ode_b2 = (const float*)d_in[16];
    const float* ode_w3 = (const float*)d_in[17];
    const float* ode_b3 = (const float*)d_in[18];
    const float* ln_g   = (const float*)d_in[19];
    const float* ln_b   = (const float*)d_in[20];
    const float* dec_w1 = (const float*)d_in[21];
    const float* dec_b1 = (const float*)d_in[22];
    const float* dec_w2 = (const float*)d_in[23];
    const float* dec_b2 = (const float*)d_in[24];
    const float* dec_w3 = (const float*)d_in[25];
    const float* dec_b3 = (const float*)d_in[26];
    float* out = (float*)d_out;

    enc_kernel<<<BB, 256>>>(x_seq, eps, enc_w1, enc_b1, enc_w2, enc_b2,
                            enc_w3, enc_b3, mu_w, mu_b, lv_w, lv_b, out);
    ode_kernel<<<BB, 128>>>(tvec, ode_w1, ode_b1, ode_w2, ode_b2,
                            ode_w3, ode_b3, ln_g, ln_b, out);
    zdiff_kernel<<<(BB * (LL - 1) * DD + 255) / 256, 256>>>(tvec, out);
    dec1_kernel<<<(BB * LL) / 16, 512>>>(out + OFF_ZT, dec_w1, dec_b1, dec_w2, dec_b2);
    dec2_kernel<<<(BB * LL) / 16, 256>>>(dec_w3, dec_b3, out);
}

// round 3
// speedup vs baseline: 1.0919x; 1.0919x over previous
#include <cuda_runtime.h>
#include <math.h>

#define BB 256
#define LL 200
#define NN 256
#define DD 16
#define KSUB 8

// Output layout: xhat | mu | logvar | z_traj | zdiff  (all float32)
#define OFF_XHAT 0
#define OFF_MU   (BB*LL*NN)
#define OFF_LV   (OFF_MU + BB*DD)
#define OFF_ZT   (OFF_LV + BB*DD)
#define OFF_ZD   (OFF_ZT + BB*LL*DD)

// decoder intermediate g2: 51200 x 512 fp32
__device__ float g_g2[51200 * 512];

__device__ __forceinline__ float siluf(float x) {
    return __fdividef(x, 1.f + __expf(-x));
}

__device__ __forceinline__ unsigned long long pack2(float lo, float hi) {
    unsigned long long r;
    asm("mov.b64 %0, {%1, %2};" : "=l"(r) : "f"(lo), "f"(hi));
    return r;
}

#define FFMA2(acc, a, b) \
    asm("fma.rn.f32x2 %0, %1, %2, %0;" : "+l"(acc) : "l"(a), "l"(b))

// ---------------------------------------------------------------------------
// Encoder: one CTA per batch row, 256 threads.
// ---------------------------------------------------------------------------
__global__ void __launch_bounds__(256)
enc_kernel(const float* __restrict__ x_seq,
           const float* __restrict__ eps,
           const float* __restrict__ w1, const float* __restrict__ b1,
           const float* __restrict__ w2, const float* __restrict__ b2,
           const float* __restrict__ w3, const float* __restrict__ b3,
           const float* __restrict__ muw, const float* __restrict__ mub,
           const float* __restrict__ lvw, const float* __restrict__ lvb,
           float* __restrict__ out)
{
    __shared__ float x0[256];
    __shared__ float h1[512];
    __shared__ float h2[256];
    __shared__ float h3[128];
    const int b = blockIdx.x;
    const int t = threadIdx.x;

    x0[t] = x_seq[(size_t)b * (LL * NN) + t];
    __syncthreads();

    for (int c = t; c < 512; c += 256) {
        float acc = b1[c];
#pragma unroll 8
        for (int j = 0; j < 256; j++) acc = fmaf(x0[j], w1[j * 512 + c], acc);
        h1[c] = fmaxf(acc, 0.f);
    }
    __syncthreads();

    {
        float acc = b2[t];
#pragma unroll 8
        for (int j = 0; j < 512; j++) acc = fmaf(h1[j], w2[j * 256 + t], acc);
        h2[t] = fmaxf(acc, 0.f);
    }
    __syncthreads();

    if (t < 128) {
        float acc = b3[t];
#pragma unroll 8
        for (int j = 0; j < 256; j++) acc = fmaf(h2[j], w3[j * 128 + t], acc);
        h3[t] = fmaxf(acc, 0.f);
    }
    __syncthreads();

    if (t < 16) {
        float m = mub[t];
        float lv = lvb[t];
#pragma unroll 8
        for (int j = 0; j < 128; j++) {
            m  = fmaf(h3[j], muw[j * 16 + t], m);
            lv = fmaf(h3[j], lvw[j * 16 + t], lv);
        }
        out[OFF_MU + b * DD + t] = m;
        out[OFF_LV + b * DD + t] = lv;
        float z0 = m + expf(0.5f * lv) * eps[b * DD + t];
        out[OFF_ZT + (size_t)b * (LL * DD) + t] = z0;
    }
}

// ---------------------------------------------------------------------------
// ODE integrator v2: one CTA per batch row, 256 threads.
// Layer-2 columns split across lane pairs (even lane: j in [0,64),
// odd lane: j in [64,128)), combined with one shfl_xor(1).
// fma.rn.f32x2 packed FMAs, ld.shared.v2.u64 paired operands.
// Only warps 0-3 (t<128) carry z/k state, layer1 and LN.
// ---------------------------------------------------------------------------
#define LOA_OFF 0
#define HIB_OFF 72
#define A2P_OFF 136
#define DZS_OFF 324

__global__ void __launch_bounds__(256, 2)
ode_kernel(const float* __restrict__ tvec,
           const float* __restrict__ w1, const float* __restrict__ b1,
           const float* __restrict__ w2, const float* __restrict__ b2,
           const float* __restrict__ w3, const float* __restrict__ b3,
           const float* __restrict__ lng, const float* __restrict__ lnb,
           float* __restrict__ out)
{
    const int t    = threadIdx.x;
    const int b    = blockIdx.x;
    const int lane = t & 31;
    const int warp = t >> 5;
    const int l16  = lane & 15;
    const int h    = lane & 1;
    const int c    = warp * 16 + (lane >> 1);   // layer2 output column
    const int oo   = t >> 4;                    // layer3 output (0..15)
    const int gg   = t & 15;                    // layer3 partial group

    __shared__ __align__(16) float smf[344];
    float* loA = smf + LOA_OFF;   // h1[0..64)
    float* hiB = smf + HIB_OFF;   // h1[64..128)
    float* a2p = smf + A2P_OFF;   // padded a2: idx = j + 4*(j>>3), size 188
    float* dzs = smf + DZS_OFF;   // 16
    const unsigned sm32 = (unsigned)__cvta_generic_to_shared(smf);

    // ---- register-resident weights ----
    unsigned long long w2h[32];   // 32 packed pairs for my 64 j's
    {
        const int j0 = 64 * h;
#pragma unroll
        for (int m = 0; m < 32; m++) {
            const int j = j0 + 2 * m;
            w2h[m] = pack2(w2[j * 128 + c], w2[(j + 1) * 128 + c]);
        }
    }
    const float b2c = b2[c];

    unsigned long long w3p[4];
#pragma unroll
    for (int i = 0; i < 4; i++) {
        const int j = 8 * gg + 2 * i;
        w3p[i] = pack2(w3[j * 16 + oo], w3[(j + 1) * 16 + oo]);
    }
    const float b3v = b3[oo];

    float w1c[16];
    float b1t = 0.f, lgv = 0.f, lbv = 0.f, zcur = 0.f;
    float* zrow = out + OFF_ZT + (size_t)b * (LL * DD);
    if (t < 128) {
#pragma unroll
        for (int j = 0; j < 16; j++) w1c[j] = w1[j * 128 + t];
        b1t = b1[t];
        lgv = lng[l16];
        lbv = lnb[l16];
        zcur = zrow[l16];
    }

    float k1 = 0.f, k2 = 0.f, k3 = 0.f, k4 = 0.f, k5 = 0.f;

    const unsigned hread  = sm32 + (h ? (HIB_OFF * 4u) : (LOA_OFF * 4u));
    const unsigned a3base = sm32 + (A2P_OFF + 12u * (unsigned)gg) * 4u;

    for (int iv = 0; iv < LL - 1; iv++) {
        const float hs = (tvec[iv + 1] - tvec[iv]) * (1.f / (float)KSUB);
        for (int sub = 0; sub < KSUB; sub++) {
#pragma unroll
            for (int s = 0; s < 6; s++) {
                // --- layer 1 (warps 0-3 only) ---
                if (t < 128) {
                    float zin;
                    if (s == 0)      zin = zcur;
                    else if (s == 1) zin = zcur + hs * (0.2f * k1);
                    else if (s == 2) zin = zcur + hs * (0.075f * k1 + 0.225f * k2);
                    else if (s == 3) zin = zcur + hs * ((44.f/45.f)*k1 - (56.f/15.f)*k2 + (32.f/9.f)*k3);
                    else if (s == 4) zin = zcur + hs * ((19372.f/6561.f)*k1 - (25360.f/2187.f)*k2
                                                     + (64448.f/6561.f)*k3 - (212.f/729.f)*k4);
                    else             zin = zcur + hs * ((9017.f/3168.f)*k1 - (355.f/33.f)*k2
                                                     + (46732.f/5247.f)*k3 + (49.f/176.f)*k4
                                                     - (5103.f/18656.f)*k5);

                    float acc = b1t;
#pragma unroll
                    for (int j = 0; j < 16; j++) {
                        float zj = __shfl_sync(0xffffffffu, zin, j, 16);
                        acc = fmaf(zj, w1c[j], acc);
                    }
                    float hv = siluf(acc);
                    if (t < 64) loA[t] = hv;
                    else        hiB[t - 64] = hv;
                }
                __syncthreads();  // BAR1: h1 ready

                // --- layer 2: half-column inner product, packed FMAs ---
                unsigned long long acc0 = 0ull, acc1 = 0ull;
#pragma unroll
                for (int m = 0; m < 16; m++) {
                    unsigned long long p0, p1;
                    asm volatile("ld.shared.v2.u64 {%0,%1}, [%2];"
                                 : "=l"(p0), "=l"(p1) : "r"(hread + 16u * m));
                    FFMA2(acc0, p0, w2h[2 * m]);
                    FFMA2(acc1, p1, w2h[2 * m + 1]);
                }
                asm("add.rn.f32x2 %0, %1, %2;" : "=l"(acc0) : "l"(acc0), "l"(acc1));
                float slo, shi;
                asm("mov.b64 {%0,%1}, %2;" : "=f"(slo), "=f"(shi) : "l"(acc0));
                float ssum = slo + shi;
                ssum += __shfl_xor_sync(0xffffffffu, ssum, 1);
                float a2v = siluf(ssum + b2c);
                if (h == 0) a2p[c + 4 * (c >> 3)] = a2v;
                __syncthreads();  // BAR2: a2 ready

                // --- layer 3: 16 partial-groups of 8, packed FMAs ---
                unsigned long long q0, q1, q2, q3;
                asm volatile("ld.shared.v2.u64 {%0,%1}, [%2];"
                             : "=l"(q0), "=l"(q1) : "r"(a3base));
                asm volatile("ld.shared.v2.u64 {%0,%1}, [%2];"
                             : "=l"(q2), "=l"(q3) : "r"(a3base + 16u));
                unsigned long long a3 = 0ull, a3b = 0ull;
                FFMA2(a3,  q0, w3p[0]);
                FFMA2(a3b, q1, w3p[1]);
                FFMA2(a3,  q2, w3p[2]);
                FFMA2(a3b, q3, w3p[3]);
                asm("add.rn.f32x2 %0, %1, %2;" : "=l"(a3) : "l"(a3), "l"(a3b));
                float plo, phi;
                asm("mov.b64 {%0,%1}, %2;" : "=f"(plo), "=f"(phi) : "l"(a3));
                float p = plo + phi;
                p += __shfl_xor_sync(0xffffffffu, p, 1, 16);
                p += __shfl_xor_sync(0xffffffffu, p, 2, 16);
                p += __shfl_xor_sync(0xffffffffu, p, 4, 16);
                p += __shfl_xor_sync(0xffffffffu, p, 8, 16);
                if (gg == 0) dzs[oo] = p + b3v;
                __syncthreads();  // BAR3: dz ready

                // --- LayerNorm + k update (warps 0-3 only) ---
                if (t < 128) {
                    float dv = dzs[l16];
                    float sm = dv;
                    float sq = dv * dv;
                    sm += __shfl_xor_sync(0xffffffffu, sm, 1, 16);
                    sq += __shfl_xor_sync(0xffffffffu, sq, 1, 16);
                    sm += __shfl_xor_sync(0xffffffffu, sm, 2, 16);
                    sq += __shfl_xor_sync(0xffffffffu, sq, 2, 16);
                    sm += __shfl_xor_sync(0xffffffffu, sm, 4, 16);
                    sq += __shfl_xor_sync(0xffffffffu, sq, 4, 16);
                    sm += __shfl_xor_sync(0xffffffffu, sm, 8, 16);
                    sq += __shfl_xor_sync(0xffffffffu, sq, 8, 16);
                    const float mn = sm * (1.f / 16.f);
                    const float vr = sq * (1.f / 16.f) - mn * mn;
                    const float kv = (dv - mn) * rsqrtf(vr + 1e-5f) * lgv + lbv;

                    if (s == 0)      k1 = kv;
                    else if (s == 1) k2 = kv;
                    else if (s == 2) k3 = kv;
                    else if (s == 3) k4 = kv;
                    else if (s == 4) k5 = kv;
                    else {
                        zcur = zcur + hs * ((35.f/384.f)*k1 + (500.f/1113.f)*k3
                                          + (125.f/192.f)*k4 - (2187.f/6784.f)*k5
                                          + (11.f/84.f)*kv);
                    }
                }
            }
        }
        if (t < 16) zrow[(iv + 1) * DD + t] = zcur;
    }
}

// ---------------------------------------------------------------------------
// Decoder stage 1: g2 = relu(relu(z W1 + b1) W2 + b2).
// 16-row tiles, 2 output columns per thread (cols t and t+256).
// ---------------------------------------------------------------------------
__global__ void __launch_bounds__(256)
dec1_kernel(const float* __restrict__ ztraj,
            const float* __restrict__ w1, const float* __restrict__ b1,
            const float* __restrict__ w2, const float* __restrict__ b2)
{
    __shared__ float zts[16 * 16];
    __shared__ float g1s[16 * 512];  // 32 KB
    const int t = threadIdx.x;
    const int row0 = blockIdx.x * 16;
    const int c0 = t, c1 = t + 256;

    zts[t] = ztraj[(size_t)row0 * 16 + t];
    float w1a[16], w1b[16];
#pragma unroll
    for (int k = 0; k < 16; k++) {
        w1a[k] = w1[k * 512 + c0];
        w1b[k] = w1[k * 512 + c1];
    }
    const float b1a = b1[c0], b1b = b1[c1];
    __syncthreads();

#pragma unroll
    for (int r = 0; r < 16; r++) {
        const float4* z4 = (const float4*)(zts + r * 16);
        float a0 = b1a, a1 = b1b;
#pragma unroll
        for (int q = 0; q < 4; q++) {
            const float4 zv = z4[q];
            a0 = fmaf(zv.x, w1a[4*q+0], a0); a1 = fmaf(zv.x, w1b[4*q+0], a1);
            a0 = fmaf(zv.y, w1a[4*q+1], a0); a1 = fmaf(zv.y, w1b[4*q+1], a1);
            a0 = fmaf(zv.z, w1a[4*q+2], a0); a1 = fmaf(zv.z, w1b[4*q+2], a1);
            a0 = fmaf(zv.w, w1a[4*q+3], a0); a1 = fmaf(zv.w, w1b[4*q+3], a1);
        }
        g1s[r * 512 + c0] = fmaxf(a0, 0.f);
        g1s[r * 512 + c1] = fmaxf(a1, 0.f);
    }
    __syncthreads();

    float acc0[16], acc1[16];
    const float bv0 = b2[c0], bv1 = b2[c1];
#pragma unroll
    for (int r = 0; r < 16; r++) { acc0[r] = bv0; acc1[r] = bv1; }

    for (int j0 = 0; j0 < 512; j0 += 4) {
        float wa0 = w2[(j0 + 0) * 512 + c0], wb0 = w2[(j0 + 0) * 512 + c1];
        float wa1 = w2[(j0 + 1) * 512 + c0], wb1 = w2[(j0 + 1) * 512 + c1];
        float wa2 = w2[(j0 + 2) * 512 + c0], wb2 = w2[(j0 + 2) * 512 + c1];
        float wa3 = w2[(j0 + 3) * 512 + c0], wb3 = w2[(j0 + 3) * 512 + c1];
#pragma unroll
        for (int r = 0; r < 16; r++) {
            const float4 gv = *(const float4*)(g1s + r * 512 + j0);
            acc0[r] = fmaf(gv.x, wa0, acc0[r]); acc1[r] = fmaf(gv.x, wb0, acc1[r]);
            acc0[r] = fmaf(gv.y, wa1, acc0[r]); acc1[r] = fmaf(gv.y, wb1, acc1[r]);
            acc0[r] = fmaf(gv.z, wa2, acc0[r]); acc1[r] = fmaf(gv.z, wb2, acc1[r]);
            acc0[r] = fmaf(gv.w, wa3, acc0[r]); acc1[r] = fmaf(gv.w, wb3, acc1[r]);
        }
    }
#pragma unroll
    for (int r = 0; r < 16; r++) {
        g_g2[(size_t)(row0 + r) * 512 + c0] = fmaxf(acc0[r], 0.f);
        g_g2[(size_t)(row0 + r) * 512 + c1] = fmaxf(acc1[r], 0.f);
    }
}

// ---------------------------------------------------------------------------
// Decoder stage 2: xhat = g2 W3 + b3.
// 16-row tiles, 2 output columns per thread (cols t and t+128).
// ---------------------------------------------------------------------------
__global__ void __launch_bounds__(128)
dec2_kernel(const float* __restrict__ w3, const float* __restrict__ b3,
            float* __restrict__ out)
{
    __shared__ float g2s[16 * 512];  // 32 KB
    const int t = threadIdx.x;
    const int row0 = blockIdx.x * 16;
    const int c0 = t, c1 = t + 128;

#pragma unroll
    for (int i = 0; i < 64; i++)
        g2s[i * 128 + t] = g_g2[(size_t)row0 * 512 + i * 128 + t];
    __syncthreads();

    float acc0[16], acc1[16];
    const float bv0 = b3[c0], bv1 = b3[c1];
#pragma unroll
    for (int r = 0; r < 16; r++) { acc0[r] = bv0; acc1[r] = bv1; }

    for (int j0 = 0; j0 < 512; j0 += 4) {
        float wa0 = w3[(j0 + 0) * 256 + c0], wb0 = w3[(j0 + 0) * 256 + c1];
        float wa1 = w3[(j0 + 1) * 256 + c0], wb1 = w3[(j0 + 1) * 256 + c1];
        float wa2 = w3[(j0 + 2) * 256 + c0], wb2 = w3[(j0 + 2) * 256 + c1];
        float wa3 = w3[(j0 + 3) * 256 + c0], wb3 = w3[(j0 + 3) * 256 + c1];
#pragma unroll
        for (int r = 0; r < 16; r++) {
            const float4 gv = *(const float4*)(g2s + r * 512 + j0);
            acc0[r] = fmaf(gv.x, wa0, acc0[r]); acc1[r] = fmaf(gv.x, wb0, acc1[r]);
            acc0[r] = fmaf(gv.y, wa1, acc0[r]); acc1[r] = fmaf(gv.y, wb1, acc1[r]);
            acc0[r] = fmaf(gv.z, wa2, acc0[r]); acc1[r] = fmaf(gv.z, wb2, acc1[r]);
            acc0[r] = fmaf(gv.w, wa3, acc0[r]); acc1[r] = fmaf(gv.w, wb3, acc1[r]);
        }
    }
#pragma unroll
    for (int r = 0; r < 16; r++) {
        out[OFF_XHAT + (size_t)(row0 + r) * 256 + c0] = acc0[r];
        out[OFF_XHAT + (size_t)(row0 + r) * 256 + c1] = acc1[r];
    }
}

// ---------------------------------------------------------------------------
// zdiff = (z_traj[:,1:,:] - z_traj[:,:-1,:]) / dt
// ---------------------------------------------------------------------------
__global__ void zdiff_kernel(const float* __restrict__ tvec, float* __restrict__ out)
{
    const int idx = blockIdx.x * blockDim.x + threadIdx.x;
    const int total = BB * (LL - 1) * DD;
    if (idx >= total) return;
    const int o = idx & 15;
    const int rest = idx >> 4;
    const int i = rest % (LL - 1);
    const int b = rest / (LL - 1);
    const float dt = tvec[i + 1] - tvec[i];
    const float* zr = out + OFF_ZT + (size_t)b * (LL * DD);
    out[OFF_ZD + idx] = (zr[(i + 1) * DD + o] - zr[i * DD + o]) / dt;
}

// ---------------------------------------------------------------------------
extern "C" void kernel_launch(void* const* d_in, const int* in_sizes, int n_in,
                              void* d_out, int out_size)
{
    const float* x_seq  = (const float*)d_in[0];
    const float* tvec   = (const float*)d_in[1];
    const float* eps    = (const float*)d_in[2];
    const float* enc_w1 = (const float*)d_in[3];
    const float* enc_b1 = (const float*)d_in[4];
    const float* enc_w2 = (const float*)d_in[5];
    const float* enc_b2 = (const float*)d_in[6];
    const float* enc_w3 = (const float*)d_in[7];
    const float* enc_b3 = (const float*)d_in[8];
    const float* mu_w   = (const float*)d_in[9];
    const float* mu_b   = (const float*)d_in[10];
    const float* lv_w   = (const float*)d_in[11];
    const float* lv_b   = (const float*)d_in[12];
    const float* ode_w1 = (const float*)d_in[13];
    const float* ode_b1 = (const float*)d_in[14];
    const float* ode_w2 = (const float*)d_in[15];
    const float* ode_b2 = (const float*)d_in[16];
    const float* ode_w3 = (const float*)d_in[17];
    const float* ode_b3 = (const float*)d_in[18];
    const float* ln_g   = (const float*)d_in[19];
    const float* ln_b   = (const float*)d_in[20];
    const float* dec_w1 = (const float*)d_in[21];
    const float* dec_b1 = (const float*)d_in[22];
    const float* dec_w2 = (const float*)d_in[23];
    const float* dec_b2 = (const float*)d_in[24];
    const float* dec_w3 = (const float*)d_in[25];
    const float* dec_b3 = (const float*)d_in[26];
    float* out = (float*)d_out;

    enc_kernel<<<BB, 256>>>(x_seq, eps, enc_w1, enc_b1, enc_w2, enc_b2,
                            enc_w3, enc_b3, mu_w, mu_b, lv_w, lv_b, out);
    ode_kernel<<<BB, 256>>>(tvec, ode_w1, ode_b1, ode_w2, ode_b2,
                            ode_w3, ode_b3, ln_g, ln_b, out);
    zdiff_kernel<<<(BB * (LL - 1) * DD + 255) / 256, 256>>>(tvec, out);
    dec1_kernel<<<(BB * LL) / 16, 256>>>(out + OFF_ZT, dec_w1, dec_b1, dec_w2, dec_b2);
    dec2_kernel<<<(BB * LL) / 16, 128>>>(dec_w3, dec_b3, out);
}